// round 1
// baseline (speedup 1.0000x reference)
#include <cuda_runtime.h>
#include <math.h>

#define NLEVELS 16
#define TSIZE (1u << 19)
#define HIDDEN 64
#define INDIM 32
#define OUTDIM 16

struct Params {
    float scale[NLEVELS];
    unsigned res[NLEVELS];
    unsigned dense_mask;
};

__global__ __launch_bounds__(256) void sdf_fused_kernel(
    const float* __restrict__ x,
    const float* __restrict__ table,
    const float* __restrict__ W0,
    const float* __restrict__ b0,
    const float* __restrict__ W1,
    const float* __restrict__ b1,
    float* __restrict__ out,
    int N, Params p)
{
    __shared__ float sW0[HIDDEN * INDIM];   // [64][32] row-major
    __shared__ float sW1T[HIDDEN * OUTDIM]; // [64][16]: sW1T[j*16+o] = W1[o][j]
    __shared__ float sB0[HIDDEN];
    __shared__ float sB1[OUTDIM];

    for (int t = threadIdx.x; t < HIDDEN * INDIM; t += blockDim.x)
        sW0[t] = W0[t];
    for (int t = threadIdx.x; t < HIDDEN * OUTDIM; t += blockDim.x) {
        int j = t >> 4, o = t & 15;
        sW1T[t] = W1[o * HIDDEN + j];
    }
    if (threadIdx.x < HIDDEN) sB0[threadIdx.x] = b0[threadIdx.x];
    if (threadIdx.x < OUTDIM) sB1[threadIdx.x] = b1[threadIdx.x];
    __syncthreads();

    int i = blockIdx.x * blockDim.x + threadIdx.x;
    if (i >= N) return;

    float x0 = x[3 * i + 0];
    float x1 = x[3 * i + 1];
    float x2 = x[3 * i + 2];
    float ux = fminf(fmaxf((x0 + 1.0f) * 0.5f, 0.0f), 1.0f);
    float uy = fminf(fmaxf((x1 + 1.0f) * 0.5f, 0.0f), 1.0f);
    float uz = fminf(fmaxf((x2 + 1.0f) * 0.5f, 0.0f), 1.0f);

    float enc[INDIM];
    const float2* tab = (const float2*)table;

#pragma unroll
    for (int l = 0; l < NLEVELS; l++) {
        float s = p.scale[l];
        float px = ux * s + 0.5f;
        float py = uy * s + 0.5f;
        float pz = uz * s + 0.5f;
        float gx = floorf(px), gy = floorf(py), gz = floorf(pz);
        float fx = px - gx, fy = py - gy, fz = pz - gz;
        unsigned cx = (unsigned)gx, cy = (unsigned)gy, cz = (unsigned)gz;

        const float2* tl = tab + (size_t)l * TSIZE;
        bool dense = (p.dense_mask >> l) & 1u;
        unsigned r = p.res[l];
        unsigned r2 = r * r;

        // compute 8 indices first so loads can all be in flight
        unsigned idx[8];
#pragma unroll
        for (int c = 0; c < 8; c++) {
            unsigned ox = c & 1u, oy = (c >> 1) & 1u, oz = (c >> 2) & 1u;
            unsigned id;
            if (dense) {
                id = (cx + ox) + (cy + oy) * r + (cz + oz) * r2;
            } else {
                id = (cx + ox) * 1u ^ (cy + oy) * 2654435761u ^ (cz + oz) * 805459861u;
            }
            idx[c] = id & (TSIZE - 1u);
        }
        float2 f[8];
#pragma unroll
        for (int c = 0; c < 8; c++) f[c] = __ldg(&tl[idx[c]]);

        float a0 = 0.0f, a1 = 0.0f;
        float wx0 = 1.0f - fx, wy0 = 1.0f - fy, wz0 = 1.0f - fz;
#pragma unroll
        for (int c = 0; c < 8; c++) {
            float w = ((c & 1) ? fx : wx0) * (((c >> 1) & 1) ? fy : wy0) * (((c >> 2) & 1) ? fz : wz0);
            a0 = fmaf(f[c].x, w, a0);
            a1 = fmaf(f[c].y, w, a1);
        }
        enc[2 * l + 0] = a0;
        enc[2 * l + 1] = a1;
    }

    // MLP: single pass over hidden units, accumulate 16 outputs
    float acc_out[OUTDIM];
#pragma unroll
    for (int o = 0; o < OUTDIM; o++) acc_out[o] = sB1[o];

#pragma unroll 1
    for (int j = 0; j < HIDDEN; j++) {
        float acc = sB0[j];
        const float4* w0r = (const float4*)&sW0[j * INDIM];
#pragma unroll
        for (int k4 = 0; k4 < INDIM / 4; k4++) {
            float4 w = w0r[k4];
            acc = fmaf(enc[4 * k4 + 0], w.x, acc);
            acc = fmaf(enc[4 * k4 + 1], w.y, acc);
            acc = fmaf(enc[4 * k4 + 2], w.z, acc);
            acc = fmaf(enc[4 * k4 + 3], w.w, acc);
        }
        // softplus_beta100
        float z = 100.0f * acc;
        float h;
        if (z > 20.0f) {
            h = acc;
        } else {
            h = log1pf(expf(fminf(z, 20.0f))) * 0.01f;
        }
        const float4* w1r = (const float4*)&sW1T[j * OUTDIM];
#pragma unroll
        for (int o4 = 0; o4 < OUTDIM / 4; o4++) {
            float4 w = w1r[o4];
            acc_out[4 * o4 + 0] = fmaf(h, w.x, acc_out[4 * o4 + 0]);
            acc_out[4 * o4 + 1] = fmaf(h, w.y, acc_out[4 * o4 + 1]);
            acc_out[4 * o4 + 2] = fmaf(h, w.z, acc_out[4 * o4 + 2]);
            acc_out[4 * o4 + 3] = fmaf(h, w.w, acc_out[4 * o4 + 3]);
        }
    }

    // outputs: [sdf (N)] then [geo (N,15)] flattened
    out[i] = acc_out[0];
    float* geo = out + N;
    size_t gbase = (size_t)i * 15;
#pragma unroll
    for (int o = 0; o < 15; o++) geo[gbase + o] = acc_out[o + 1];
}

extern "C" void kernel_launch(void* const* d_in, const int* in_sizes, int n_in,
                              void* d_out, int out_size)
{
    const float* x     = (const float*)d_in[0];
    const float* table = (const float*)d_in[1];
    const float* W0    = (const float*)d_in[2];
    const float* b0    = (const float*)d_in[3];
    const float* W1    = (const float*)d_in[4];
    const float* b1    = (const float*)d_in[5];
    float* out = (float*)d_out;

    int N = in_sizes[0] / 3;

    Params p;
    p.dense_mask = 0;
    const double pls = exp2(7.0 / 15.0); // per-level scale, matches np.exp2(np.log2(128)/15)
    for (int l = 0; l < NLEVELS; l++) {
        double sc = 16.0 * pow(pls, (double)l) - 1.0;
        p.scale[l] = (float)sc;
        int res = (int)ceil(sc) + 1;
        p.res[l] = (unsigned)res;
        long long r3 = (long long)res * res * res;
        if (r3 <= (long long)TSIZE) p.dense_mask |= (1u << l);
    }

    int threads = 256;
    int blocks = (N + threads - 1) / threads;
    sdf_fused_kernel<<<blocks, threads>>>(x, table, W0, b0, W1, b1, out, N, p);
}

// round 2
// speedup vs baseline: 1.0451x; 1.0451x over previous
#include <cuda_runtime.h>
#include <math.h>

#define NLEVELS 16
#define TSIZE (1u << 19)
#define TMASK (TSIZE - 1u)
#define HIDDEN 64
#define INDIM 32
#define OUTDIM 16
#define P2 2654435761u
#define P3 805459861u
#define TPB 256

__constant__ float cW0[HIDDEN * INDIM];   // [j][k] row-major (as given)
__constant__ float cW1[OUTDIM * HIDDEN];  // [o][j] row-major (as given)
__constant__ float cB0[HIDDEN];
__constant__ float cB1[OUTDIM];

struct Params {
    float scale[NLEVELS];
    unsigned res[NLEVELS];
    unsigned dense_mask;
};

__global__ __launch_bounds__(TPB) void sdf_fused_kernel(
    const float* __restrict__ x,
    const float* __restrict__ table,
    float* __restrict__ out,
    int N, Params p)
{
    __shared__ float sGeo[TPB * 15];

    int tid = threadIdx.x;
    int iBase = blockIdx.x * TPB;
    int i = iBase + tid;
    bool valid = (i < N);
    int ii = valid ? i : 0;

    float x0 = x[3 * ii + 0];
    float x1 = x[3 * ii + 1];
    float x2 = x[3 * ii + 2];
    float ux = fminf(fmaxf((x0 + 1.0f) * 0.5f, 0.0f), 1.0f);
    float uy = fminf(fmaxf((x1 + 1.0f) * 0.5f, 0.0f), 1.0f);
    float uz = fminf(fmaxf((x2 + 1.0f) * 0.5f, 0.0f), 1.0f);

    float enc[INDIM];
    const float2* __restrict__ tab = (const float2*)table;

#pragma unroll
    for (int l = 0; l < NLEVELS; l++) {
        float s = p.scale[l];
        float px = fmaf(ux, s, 0.5f);
        float py = fmaf(uy, s, 0.5f);
        float pz = fmaf(uz, s, 0.5f);
        float gx = floorf(px), gy = floorf(py), gz = floorf(pz);
        float fx = px - gx, fy = py - gy, fz = pz - gz;
        unsigned cx = (unsigned)gx, cy = (unsigned)gy, cz = (unsigned)gz;

        const float2* __restrict__ tl = tab + (size_t)l * TSIZE;
        const float4* __restrict__ tl4 = (const float4*)tl;
        bool dense = (p.dense_mask >> l) & 1u;
        unsigned r = p.res[l];
        unsigned r2 = r * r;

        float wx0 = 1.0f - fx;
        float wy0 = 1.0f - fy, wz0 = 1.0f - fz;
        float a0 = 0.0f, a1 = 0.0f;

#pragma unroll
        for (int c = 0; c < 4; c++) {
            unsigned oy = c & 1u, oz = (c >> 1) & 1u;
            unsigned jlo, jhi;
            if (dense) {
                unsigned b = cx + (cy + oy) * r + (cz + oz) * r2;
                jlo = b & TMASK;
                jhi = (b + 1u) & TMASK;
            } else {
                unsigned H = (cy + oy) * P2 ^ (cz + oz) * P3;
                jlo = (cx ^ H) & TMASK;
                jhi = ((cx + 1u) ^ H) & TMASK;
            }
            float2 flo, fhi;
            if ((jlo ^ jhi) == 1u) {
                // the two corners live in one aligned 16B block
                float4 v = __ldg(tl4 + (jlo >> 1));
                if (jlo & 1u) {
                    flo = make_float2(v.z, v.w);
                    fhi = make_float2(v.x, v.y);
                } else {
                    flo = make_float2(v.x, v.y);
                    fhi = make_float2(v.z, v.w);
                }
            } else {
                flo = __ldg(tl + jlo);
                fhi = __ldg(tl + jhi);
            }
            float wyz = (oy ? fy : wy0) * (oz ? fz : wz0);
            a0 = fmaf(fmaf(fhi.x, fx, flo.x * wx0), wyz, a0);
            a1 = fmaf(fmaf(fhi.y, fx, flo.y * wx0), wyz, a1);
        }
        enc[2 * l + 0] = a0;
        enc[2 * l + 1] = a1;
    }

    // ---- MLP: weights from constant memory (uniform port, off L1tex) ----
    float acc[OUTDIM];
#pragma unroll
    for (int o = 0; o < OUTDIM; o++) acc[o] = cB1[o];

#pragma unroll 8
    for (int j = 0; j < HIDDEN; j++) {
        float h = cB0[j];
#pragma unroll
        for (int k = 0; k < INDIM; k++)
            h = fmaf(enc[k], cW0[j * INDIM + k], h);
        // softplus beta=100 (matches reference)
        float z = 100.0f * h;
        float a = (z > 20.0f) ? h : (log1pf(expf(z)) * 0.01f);
#pragma unroll
        for (int o = 0; o < OUTDIM; o++)
            acc[o] = fmaf(a, cW1[o * HIDDEN + j], acc[o]);
    }

    // ---- outputs: [sdf(N)] then [geo(N,15)]; geo staged for coalescing ----
#pragma unroll
    for (int o = 0; o < 15; o++) sGeo[tid * 15 + o] = acc[o + 1];
    if (valid) out[i] = acc[0];
    __syncthreads();

    float* __restrict__ geo = out + N;
    size_t gbase = (size_t)iBase * 15;
    int total = (N - iBase) * 15;
    if (total > TPB * 15) total = TPB * 15;
    for (int t = tid; t < total; t += TPB)
        geo[gbase + t] = sGeo[t];
}

extern "C" void kernel_launch(void* const* d_in, const int* in_sizes, int n_in,
                              void* d_out, int out_size)
{
    const float* x     = (const float*)d_in[0];
    const float* table = (const float*)d_in[1];
    const float* W0    = (const float*)d_in[2];
    const float* b0    = (const float*)d_in[3];
    const float* W1    = (const float*)d_in[4];
    const float* b1    = (const float*)d_in[5];
    float* out = (float*)d_out;

    int N = in_sizes[0] / 3;

    cudaMemcpyToSymbolAsync(cW0, W0, HIDDEN * INDIM * sizeof(float), 0,
                            cudaMemcpyDeviceToDevice, 0);
    cudaMemcpyToSymbolAsync(cW1, W1, OUTDIM * HIDDEN * sizeof(float), 0,
                            cudaMemcpyDeviceToDevice, 0);
    cudaMemcpyToSymbolAsync(cB0, b0, HIDDEN * sizeof(float), 0,
                            cudaMemcpyDeviceToDevice, 0);
    cudaMemcpyToSymbolAsync(cB1, b1, OUTDIM * sizeof(float), 0,
                            cudaMemcpyDeviceToDevice, 0);

    Params p;
    p.dense_mask = 0;
    const double pls = exp2(7.0 / 15.0);
    for (int l = 0; l < NLEVELS; l++) {
        double sc = 16.0 * pow(pls, (double)l) - 1.0;
        p.scale[l] = (float)sc;
        int res = (int)ceil(sc) + 1;
        p.res[l] = (unsigned)res;
        long long r3 = (long long)res * res * res;
        if (r3 <= (long long)TSIZE) p.dense_mask |= (1u << l);
    }

    int blocks = (N + TPB - 1) / TPB;
    sdf_fused_kernel<<<blocks, TPB>>>(x, table, out, N, p);
}

// round 4
// speedup vs baseline: 1.0793x; 1.0328x over previous
#include <cuda_runtime.h>
#include <math.h>

#define NLEVELS 16
#define TSIZE (1u << 19)
#define TMASK (TSIZE - 1u)
#define HIDDEN 64
#define INDIM 32
#define OUTDIM 16
#define P2 2654435761u
#define P3 805459861u
#define TPB 256
#define NDENSE 5

__constant__ float cW0[HIDDEN * INDIM];   // [j][k] row-major
__constant__ float cW1[OUTDIM * HIDDEN];  // [o][j] row-major (native layout)
__constant__ float cB0[HIDDEN];
__constant__ float cB1[OUTDIM];

__device__ __constant__ const unsigned kRES[NDENSE] = {16u, 23u, 31u, 43u, 59u};

struct Params {
    float scale[NLEVELS];
};

// Predicated vector load: r = cond ? *addr : fb, with NO branch (single @p LDG).
__device__ __forceinline__ float2 cond_ldg_f2(const float2* addr, unsigned cond, float2 fb) {
    float2 r = fb;
    asm("{\n\t"
        ".reg .pred p;\n\t"
        "setp.ne.u32 p, %2, 0;\n\t"
        "@p ld.global.nc.v2.f32 {%0,%1}, [%3];\n\t"
        "}"
        : "+f"(r.x), "+f"(r.y)
        : "r"(cond), "l"(addr));
    return r;
}

__global__ __launch_bounds__(TPB) void sdf_fused_kernel(
    const float* __restrict__ x,
    const float* __restrict__ table,
    float* __restrict__ out,
    int N, Params p)
{
    __shared__ float sGeo[TPB * 15];

    int tid = threadIdx.x;
    int iBase = blockIdx.x * TPB;
    int i = iBase + tid;
    bool valid = (i < N);
    int ii = valid ? i : 0;

    float x0 = x[3 * ii + 0];
    float x1 = x[3 * ii + 1];
    float x2 = x[3 * ii + 2];
    float ux = fminf(fmaxf((x0 + 1.0f) * 0.5f, 0.0f), 1.0f);
    float uy = fminf(fmaxf((x1 + 1.0f) * 0.5f, 0.0f), 1.0f);
    float uz = fminf(fmaxf((x2 + 1.0f) * 0.5f, 0.0f), 1.0f);

    float enc[INDIM];
    const float2* __restrict__ tab = (const float2*)table;

#pragma unroll
    for (int l = 0; l < NLEVELS; l++) {
        float s = p.scale[l];
        float px = fmaf(ux, s, 0.5f);
        float py = fmaf(uy, s, 0.5f);
        float pz = fmaf(uz, s, 0.5f);
        float gx = floorf(px), gy = floorf(py), gz = floorf(pz);
        float fx = px - gx, fy = py - gy, fz = pz - gz;
        unsigned cx = (unsigned)gx, cy = (unsigned)gy, cz = (unsigned)gz;

        const float2* __restrict__ tl = tab + (size_t)l * TSIZE;
        const float4* __restrict__ tl4 = (const float4*)tl;

        float wx0 = 1.0f - fx;
        float wy0 = 1.0f - fy, wz0 = 1.0f - fz;
        float a0 = 0.0f, a1 = 0.0f;

        // per-level reusable index terms
        unsigned ty0, ty1, tz0, tz1;
        if (l < NDENSE) {
            unsigned r = kRES[l], r2 = r * r;
            ty0 = cy * r;  ty1 = ty0 + r;
            tz0 = cz * r2; tz1 = tz0 + r2;
        } else {
            ty0 = cy * P2; ty1 = ty0 + P2;
            tz0 = cz * P3; tz1 = tz0 + P3;
        }

#pragma unroll
        for (int c = 0; c < 4; c++) {
            unsigned oy = c & 1u, oz = (c >> 1) & 1u;
            unsigned tyz = (oy ? ty1 : ty0);
            unsigned tzz = (oz ? tz1 : tz0);
            unsigned jlo, jhi;
            if (l < NDENSE) {
                unsigned b = cx + tyz + tzz;   // < T for all dense levels
                jlo = b;
                jhi = b + 1u;
            } else {
                unsigned H = tyz ^ tzz;
                jlo = (cx ^ H) & TMASK;
                jhi = ((cx + 1u) ^ H) & TMASK;
            }
            // aligned 16B block containing jlo (and, often, jhi)
            float4 v = __ldg(tl4 + (jlo >> 1));
            unsigned odd = jlo & 1u;
            float2 flo = odd ? make_float2(v.z, v.w) : make_float2(v.x, v.y);
            float2 oth = odd ? make_float2(v.x, v.y) : make_float2(v.z, v.w);
            unsigned notpair = ((jlo ^ jhi) != 1u) ? 1u : 0u;
            float2 fhi = cond_ldg_f2(tl + jhi, notpair, oth);

            float wyz = (oy ? fy : wy0) * (oz ? fz : wz0);
            a0 = fmaf(fmaf(fhi.x, fx, flo.x * wx0), wyz, a0);
            a1 = fmaf(fmaf(fhi.y, fx, flo.y * wx0), wyz, a1);
        }
        enc[2 * l + 0] = a0;
        enc[2 * l + 1] = a1;
    }

    // ---- MLP (weights in constant memory; warp-uniform -> constant port) ----
    float acc[OUTDIM];
#pragma unroll
    for (int o = 0; o < OUTDIM; o++) acc[o] = cB1[o];

    const float4* __restrict__ w0v = (const float4*)cW0;

#pragma unroll 8
    for (int j = 0; j < HIDDEN; j++) {
        float h = cB0[j];
#pragma unroll
        for (int k4 = 0; k4 < INDIM / 4; k4++) {
            float4 w = w0v[j * (INDIM / 4) + k4];
            h = fmaf(enc[4 * k4 + 0], w.x, h);
            h = fmaf(enc[4 * k4 + 1], w.y, h);
            h = fmaf(enc[4 * k4 + 2], w.z, h);
            h = fmaf(enc[4 * k4 + 3], w.w, h);
        }
        // softplus beta=100, branchless: fast intrinsics + select
        float z = 100.0f * h;
        float sp = __logf(1.0f + __expf(z)) * 0.01f;
        float a = (z > 20.0f) ? h : sp;
#pragma unroll
        for (int o = 0; o < OUTDIM; o++)
            acc[o] = fmaf(a, cW1[o * HIDDEN + j], acc[o]);
    }

    // ---- outputs: [sdf(N)] then [geo(N,15)], geo staged for coalescing ----
#pragma unroll
    for (int o = 0; o < 15; o++) sGeo[tid * 15 + o] = acc[o + 1];
    if (valid) out[i] = acc[0];
    __syncthreads();

    float* __restrict__ geo = out + N;
    size_t gbase = (size_t)iBase * 15;
    int total = (N - iBase) * 15;
    if (total > TPB * 15) total = TPB * 15;
    for (int t = tid; t < total; t += TPB)
        geo[gbase + t] = sGeo[t];
}

extern "C" void kernel_launch(void* const* d_in, const int* in_sizes, int n_in,
                              void* d_out, int out_size)
{
    const float* x     = (const float*)d_in[0];
    const float* table = (const float*)d_in[1];
    const float* W0    = (const float*)d_in[2];
    const float* b0    = (const float*)d_in[3];
    const float* W1    = (const float*)d_in[4];
    const float* b1    = (const float*)d_in[5];
    float* out = (float*)d_out;

    int N = in_sizes[0] / 3;

    cudaMemcpyToSymbolAsync(cW0, W0, HIDDEN * INDIM * sizeof(float), 0,
                            cudaMemcpyDeviceToDevice, 0);
    cudaMemcpyToSymbolAsync(cW1, W1, OUTDIM * HIDDEN * sizeof(float), 0,
                            cudaMemcpyDeviceToDevice, 0);
    cudaMemcpyToSymbolAsync(cB0, b0, HIDDEN * sizeof(float), 0,
                            cudaMemcpyDeviceToDevice, 0);
    cudaMemcpyToSymbolAsync(cB1, b1, OUTDIM * sizeof(float), 0,
                            cudaMemcpyDeviceToDevice, 0);

    Params p;
    const double pls = exp2(7.0 / 15.0);
    for (int l = 0; l < NLEVELS; l++) {
        double sc = 16.0 * pow(pls, (double)l) - 1.0;
        p.scale[l] = (float)sc;
    }

    int blocks = (N + TPB - 1) / TPB;
    sdf_fused_kernel<<<blocks, TPB>>>(x, table, out, N, p);
}